// round 6
// baseline (speedup 1.0000x reference)
#include <cuda_runtime.h>
#include <cstdint>

#define NBATCH 256
#define NSRC   512
#define NPRED  128
#define NDIM   512

// Scratch (device globals are the sanctioned alloc-free workaround).
static __device__ __align__(128) float g_Q[(size_t)NBATCH * NPRED * NDIM];  // 67 MB
static __device__ __align__(128) float g_S[(size_t)NBATCH * NPRED * NSRC];  // 67 MB

__device__ __forceinline__ uint32_t f2tf(float f) {
    uint32_t u;
    asm("cvt.rna.tf32.f32 %0, %1;" : "=r"(u) : "f"(f));
    return u;
}

__device__ __forceinline__ void mma_tf32(float (&d)[4], const uint32_t* a, const uint32_t* b) {
    asm volatile(
        "mma.sync.aligned.m16n8k8.row.col.f32.tf32.tf32.f32 "
        "{%0,%1,%2,%3}, {%4,%5,%6,%7}, {%8,%9}, {%0,%1,%2,%3};\n"
        : "+f"(d[0]), "+f"(d[1]), "+f"(d[2]), "+f"(d[3])
        : "r"(a[0]), "r"(a[1]), "r"(a[2]), "r"(a[3]), "r"(b[0]), "r"(b[1]));
}

// C (128 x 512) += A (128 x 512) * op(B); this CTA computes N-columns [blockIdx.x*128, +128).
// BT=true : B is (512 n-rows x 512 k-cols) row-major  -> C = A * B^T
// BT=false: B is (512 k-rows x 512 n-cols) row-major  -> C = A * B
// SPLIT=true: 3xTF32 (hi/lo decomposition) for ~fp32 accuracy on the score path.
template <bool BT, bool SPLIT>
__device__ __forceinline__ void gemm_tile(const float* __restrict__ Ab,
                                          const float* __restrict__ Bb,
                                          float* __restrict__ Cb) {
    constexpr int ASTR = 20;                 // (20r + c) % 32 distinct -> conflict-free LDS
    constexpr int BROWS = BT ? 128 : 16;
    constexpr int BSTR = BT ? 20 : 136;      // NN: (136k + n) % 32 = (8k + n) % 32 distinct

    __shared__ uint32_t As_h[128][ASTR];
    __shared__ uint32_t Bs_h[BROWS][BSTR];
    __shared__ uint32_t As_l[SPLIT ? 128 : 1][SPLIT ? ASTR : 1];
    __shared__ uint32_t Bs_l[SPLIT ? BROWS : 1][SPLIT ? BSTR : 1];

    const int tid  = threadIdx.x;
    const int lane = tid & 31;
    const int warp = tid >> 5;
    const int wm = (warp >> 2) << 6;   // 0 or 64
    const int wn = (warp & 3) << 5;    // 0,32,64,96

    const float* Bp = BT ? (Bb + (size_t)blockIdx.x * 128 * 512)
                         : (Bb + blockIdx.x * 128);
    float* Cp = Cb + blockIdx.x * 128;

    float acc[4][4][4];
#pragma unroll
    for (int i = 0; i < 4; i++)
#pragma unroll
        for (int j = 0; j < 4; j++)
#pragma unroll
            for (int r = 0; r < 4; r++) acc[i][j][r] = 0.0f;

    const int alr = tid >> 2;          // 0..63
    const int alc = (tid & 3) << 2;    // 0,4,8,12
    const int blr = tid >> 5;          // 0..7
    const int blc = lane << 2;         // 0..124

    for (int k0 = 0; k0 < 512; k0 += 16) {
        // ---- load A tile (128 x 16), k-major ----
#pragma unroll
        for (int it = 0; it < 2; it++) {
            int row = alr + it * 64;
            float4 v = *reinterpret_cast<const float4*>(Ab + (size_t)row * 512 + k0 + alc);
            uint32_t hx = f2tf(v.x), hy = f2tf(v.y), hz = f2tf(v.z), hw = f2tf(v.w);
            *reinterpret_cast<uint4*>(&As_h[row][alc]) = make_uint4(hx, hy, hz, hw);
            if (SPLIT) {
                uint32_t lx = f2tf(v.x - __uint_as_float(hx));
                uint32_t ly = f2tf(v.y - __uint_as_float(hy));
                uint32_t lz = f2tf(v.z - __uint_as_float(hz));
                uint32_t lw = f2tf(v.w - __uint_as_float(hw));
                *reinterpret_cast<uint4*>(&As_l[row][alc]) = make_uint4(lx, ly, lz, lw);
            }
        }
        // ---- load B tile ----
        if (BT) {
#pragma unroll
            for (int it = 0; it < 2; it++) {
                int row = alr + it * 64;   // n within tile
                float4 v = *reinterpret_cast<const float4*>(Bp + (size_t)row * 512 + k0 + alc);
                uint32_t hx = f2tf(v.x), hy = f2tf(v.y), hz = f2tf(v.z), hw = f2tf(v.w);
                *reinterpret_cast<uint4*>(&Bs_h[row][alc]) = make_uint4(hx, hy, hz, hw);
                if (SPLIT) {
                    uint32_t lx = f2tf(v.x - __uint_as_float(hx));
                    uint32_t ly = f2tf(v.y - __uint_as_float(hy));
                    uint32_t lz = f2tf(v.z - __uint_as_float(hz));
                    uint32_t lw = f2tf(v.w - __uint_as_float(hw));
                    *reinterpret_cast<uint4*>(&Bs_l[row][alc]) = make_uint4(lx, ly, lz, lw);
                }
            }
        } else {
#pragma unroll
            for (int it = 0; it < 2; it++) {
                int row = blr + it * 8;    // k within tile
                float4 v = *reinterpret_cast<const float4*>(Bp + (size_t)(k0 + row) * 512 + blc);
                uint32_t hx = f2tf(v.x), hy = f2tf(v.y), hz = f2tf(v.z), hw = f2tf(v.w);
                *reinterpret_cast<uint4*>(&Bs_h[row][blc]) = make_uint4(hx, hy, hz, hw);
                if (SPLIT) {
                    uint32_t lx = f2tf(v.x - __uint_as_float(hx));
                    uint32_t ly = f2tf(v.y - __uint_as_float(hy));
                    uint32_t lz = f2tf(v.z - __uint_as_float(hz));
                    uint32_t lw = f2tf(v.w - __uint_as_float(hw));
                    *reinterpret_cast<uint4*>(&Bs_l[row][blc]) = make_uint4(lx, ly, lz, lw);
                }
            }
        }
        __syncthreads();

        // ---- compute: 2 k-steps of 8 ----
#pragma unroll
        for (int kk = 0; kk < 2; kk++) {
            const int c0 = kk * 8 + (lane & 3);
            const int g4 = lane >> 2;
            uint32_t bh[4][2], bl[4][2];
#pragma unroll
            for (int j = 0; j < 4; j++) {
                int n0 = wn + j * 8 + g4;
                if (BT) {
                    bh[j][0] = Bs_h[n0][c0];
                    bh[j][1] = Bs_h[n0][c0 + 4];
                    if (SPLIT) {
                        bl[j][0] = Bs_l[n0][c0];
                        bl[j][1] = Bs_l[n0][c0 + 4];
                    }
                } else {
                    bh[j][0] = Bs_h[c0][n0];
                    bh[j][1] = Bs_h[c0 + 4][n0];
                    if (SPLIT) {
                        bl[j][0] = Bs_l[c0][n0];
                        bl[j][1] = Bs_l[c0 + 4][n0];
                    }
                }
            }
#pragma unroll
            for (int i = 0; i < 4; i++) {
                int r0 = wm + i * 16 + g4;
                uint32_t ah[4] = {As_h[r0][c0], As_h[r0 + 8][c0],
                                  As_h[r0][c0 + 4], As_h[r0 + 8][c0 + 4]};
                uint32_t al[4];
                if (SPLIT) {
                    al[0] = As_l[r0][c0];
                    al[1] = As_l[r0 + 8][c0];
                    al[2] = As_l[r0][c0 + 4];
                    al[3] = As_l[r0 + 8][c0 + 4];
                }
#pragma unroll
                for (int j = 0; j < 4; j++) {
                    if (SPLIT) {
                        mma_tf32(acc[i][j], ah, bl[j]);  // hi * lo
                        mma_tf32(acc[i][j], al, bh[j]);  // lo * hi
                    }
                    mma_tf32(acc[i][j], ah, bh[j]);      // hi * hi
                }
            }
        }
        __syncthreads();
    }

    // ---- epilogue ----
#pragma unroll
    for (int i = 0; i < 4; i++) {
        int r0 = wm + i * 16 + (lane >> 2);
#pragma unroll
        for (int j = 0; j < 4; j++) {
            int n0 = wn + j * 8 + ((lane & 3) << 1);
            *reinterpret_cast<float2*>(Cp + (size_t)r0 * 512 + n0) =
                make_float2(acc[i][j][0], acc[i][j][1]);
            *reinterpret_cast<float2*>(Cp + (size_t)(r0 + 8) * 512 + n0) =
                make_float2(acc[i][j][2], acc[i][j][3]);
        }
    }
}

// Q[b] = dec[b] (128x512) @ W^T  — 3xTF32 split
__global__ __launch_bounds__(256, 2) void k_query(const float* __restrict__ dec,
                                                  const float* __restrict__ W) {
    size_t b = blockIdx.z;
    gemm_tile<true, true>(dec + b * NPRED * NDIM, W, g_Q + b * NPRED * NDIM);
}

// S[b] = Q[b] (128x512) @ enc[b]^T  — 3xTF32 split
__global__ __launch_bounds__(256, 2) void k_scores(const float* __restrict__ enc) {
    size_t b = blockIdx.z;
    gemm_tile<true, true>(g_Q + b * NPRED * NDIM, enc + b * NSRC * NDIM,
                          g_S + b * NPRED * NSRC);
}

// C[b] = P[b] (128x512) @ enc[b]  — single-pass TF32 (P near-one-hot, error ~2e-4)
__global__ __launch_bounds__(256, 2) void k_context(const float* __restrict__ enc,
                                                    float* __restrict__ out) {
    size_t b = blockIdx.z;
    gemm_tile<false, false>(g_S + b * NPRED * NSRC, enc + b * NSRC * NDIM,
                            out + b * NPRED * NDIM);
}

// Masked softmax over SRC=512, one warp per (b, p) row, in place on g_S.
// mask is INT32 (harness converts jnp.bool_ to int32): nonzero -> masked.
__global__ __launch_bounds__(256) void k_softmax(const int* __restrict__ mask) {
    int gw = (blockIdx.x * 256 + threadIdx.x) >> 5;   // row id, 0..32767
    int lane = threadIdx.x & 31;
    float* row = g_S + (size_t)gw * NSRC;
    const int* mrow = mask + (size_t)(gw >> 7) * NSRC;  // b = row / PRED

    float v[16];
    float m = -1e30f;
#pragma unroll
    for (int i = 0; i < 4; i++) {
        int s = i * 128 + lane * 4;
        float4 x = *reinterpret_cast<const float4*>(row + s);
        int4 mk = *reinterpret_cast<const int4*>(mrow + s);
        v[i * 4 + 0] = mk.x ? -1e30f : x.x;
        v[i * 4 + 1] = mk.y ? -1e30f : x.y;
        v[i * 4 + 2] = mk.z ? -1e30f : x.z;
        v[i * 4 + 3] = mk.w ? -1e30f : x.w;
        m = fmaxf(m, fmaxf(fmaxf(v[i * 4 + 0], v[i * 4 + 1]),
                           fmaxf(v[i * 4 + 2], v[i * 4 + 3])));
    }
#pragma unroll
    for (int o = 16; o; o >>= 1) m = fmaxf(m, __shfl_xor_sync(0xffffffffu, m, o));

    float sum = 0.0f;
#pragma unroll
    for (int i = 0; i < 16; i++) {
        v[i] = __expf(v[i] - m);
        sum += v[i];
    }
#pragma unroll
    for (int o = 16; o; o >>= 1) sum += __shfl_xor_sync(0xffffffffu, sum, o);
    float inv = 1.0f / sum;

#pragma unroll
    for (int i = 0; i < 4; i++) {
        int s = i * 128 + lane * 4;
        *reinterpret_cast<float4*>(row + s) =
            make_float4(v[i * 4 + 0] * inv, v[i * 4 + 1] * inv,
                        v[i * 4 + 2] * inv, v[i * 4 + 3] * inv);
    }
}

extern "C" void kernel_launch(void* const* d_in, const int* in_sizes, int n_in,
                              void* d_out, int out_size) {
    // Resolve inputs by element count (robust to ordering): enc 67108864,
    // dec 16777216, W 262144, mask 131072 — all distinct.
    const float* enc = nullptr;
    const float* dec = nullptr;
    const float* W = nullptr;
    const int* mask = nullptr;
    for (int i = 0; i < n_in; i++) {
        int n = in_sizes[i];
        if (n == NBATCH * NSRC * NDIM)        enc  = (const float*)d_in[i];
        else if (n == NBATCH * NPRED * NDIM)  dec  = (const float*)d_in[i];
        else if (n == NDIM * NDIM)            W    = (const float*)d_in[i];
        else if (n == NBATCH * NSRC)          mask = (const int*)d_in[i];
    }
    float* out = (float*)d_out;

    dim3 g(4, 1, NBATCH);  // 4 N-tiles of 128, one z-slice per batch
    k_query<<<g, 256>>>(dec, W);
    k_scores<<<g, 256>>>(enc);
    k_softmax<<<(NBATCH * NPRED) / 8, 256>>>(mask);  // 8 warp-rows per block
    k_context<<<g, 256>>>(enc, out);
}

// round 8
// speedup vs baseline: 1.3188x; 1.3188x over previous
#include <cuda_runtime.h>
#include <cuda_fp16.h>
#include <cstdint>

#define NBATCH 256
#define NSRC   512
#define NPRED  128
#define NDIM   512

// Scratch (device globals are the sanctioned alloc-free workaround).
static __device__ __align__(128) float g_Q[(size_t)NBATCH * NPRED * NDIM];  // 67 MB
static __device__ __align__(128) float g_S[(size_t)NBATCH * NPRED * NSRC];  // 67 MB

__device__ __forceinline__ uint32_t f2tf(float f) {
    uint32_t u;
    asm("cvt.rna.tf32.f32 %0, %1;" : "=r"(u) : "f"(f));
    return u;
}

__device__ __forceinline__ void mma_tf32(float (&d)[4], const uint32_t* a, const uint32_t* b) {
    asm volatile(
        "mma.sync.aligned.m16n8k8.row.col.f32.tf32.tf32.f32 "
        "{%0,%1,%2,%3}, {%4,%5,%6,%7}, {%8,%9}, {%0,%1,%2,%3};\n"
        : "+f"(d[0]), "+f"(d[1]), "+f"(d[2]), "+f"(d[3])
        : "r"(a[0]), "r"(a[1]), "r"(a[2]), "r"(a[3]), "r"(b[0]), "r"(b[1]));
}

__device__ __forceinline__ void mma_f16(float (&d)[4], const uint32_t* a, const uint32_t* b) {
    asm volatile(
        "mma.sync.aligned.m16n8k16.row.col.f32.f16.f16.f32 "
        "{%0,%1,%2,%3}, {%4,%5,%6,%7}, {%8,%9}, {%0,%1,%2,%3};\n"
        : "+f"(d[0]), "+f"(d[1]), "+f"(d[2]), "+f"(d[3])
        : "r"(a[0]), "r"(a[1]), "r"(a[2]), "r"(a[3]), "r"(b[0]), "r"(b[1]));
}

// ============================================================================
// fp16 hi/lo split GEMM-NT (score path): C(128x512 slice) = A(128x512) * B^T.
// B is n-major rows x k-cols, caller pre-offsets to this CTA's 128 n-rows.
// x = h + l (fp16 each, 22-bit effective mantissa); D = Ah*Bh + Ah*Bl + Al*Bh.
// BK=32, register-staged global loads overlap the mma phase.
// ============================================================================
#define HPAD 40  // fp16 stride: bank word = 20*row + k/2 -> conflict-free

__device__ __forceinline__ void split_gemm_nt(const float* __restrict__ Ab,
                                              const float* __restrict__ Bp,
                                              float* __restrict__ Cp) {
    __shared__ __half Ah[128][HPAD], Al[128][HPAD];
    __shared__ __half Bh[128][HPAD], Bl[128][HPAD];

    const int tid  = threadIdx.x;
    const int lane = tid & 31;
    const int warp = tid >> 5;
    const int wm = (warp >> 2) << 6;   // 0 or 64
    const int wn = (warp & 3) << 5;    // 0,32,64,96
    const int g  = lane >> 2;          // 0..7
    const int tg = lane & 3;           // 0..3

    // load mapping: 2 threads per row, each covers 16 k (4 float4)
    const int lrow = tid >> 1;          // 0..127
    const int lk0  = (tid & 1) << 4;    // 0 or 16

    float acc[4][4][4];
#pragma unroll
    for (int i = 0; i < 4; i++)
#pragma unroll
        for (int j = 0; j < 4; j++)
#pragma unroll
            for (int r = 0; r < 4; r++) acc[i][j][r] = 0.0f;

    float4 sa[4], sb[4];

    auto do_loads = [&](int k0) {
#pragma unroll
        for (int it = 0; it < 4; it++) {
            sa[it] = *reinterpret_cast<const float4*>(Ab + (size_t)lrow * 512 + k0 + lk0 + it * 4);
            sb[it] = *reinterpret_cast<const float4*>(Bp + (size_t)lrow * 512 + k0 + lk0 + it * 4);
        }
    };

    auto do_store = [&]() {
#pragma unroll
        for (int it = 0; it < 4; it++) {
            int kk = lk0 + it * 4;
            {
                float4 v = sa[it];
                __half hx = __float2half_rn(v.x), hy = __float2half_rn(v.y);
                __half hz = __float2half_rn(v.z), hw = __float2half_rn(v.w);
                *reinterpret_cast<__half2*>(&Ah[lrow][kk])     = __halves2half2(hx, hy);
                *reinterpret_cast<__half2*>(&Ah[lrow][kk + 2]) = __halves2half2(hz, hw);
                __half lx = __float2half_rn(v.x - __half2float(hx));
                __half ly = __float2half_rn(v.y - __half2float(hy));
                __half lz = __float2half_rn(v.z - __half2float(hz));
                __half lw = __float2half_rn(v.w - __half2float(hw));
                *reinterpret_cast<__half2*>(&Al[lrow][kk])     = __halves2half2(lx, ly);
                *reinterpret_cast<__half2*>(&Al[lrow][kk + 2]) = __halves2half2(lz, lw);
            }
            {
                float4 v = sb[it];
                __half hx = __float2half_rn(v.x), hy = __float2half_rn(v.y);
                __half hz = __float2half_rn(v.z), hw = __float2half_rn(v.w);
                *reinterpret_cast<__half2*>(&Bh[lrow][kk])     = __halves2half2(hx, hy);
                *reinterpret_cast<__half2*>(&Bh[lrow][kk + 2]) = __halves2half2(hz, hw);
                __half lx = __float2half_rn(v.x - __half2float(hx));
                __half ly = __float2half_rn(v.y - __half2float(hy));
                __half lz = __float2half_rn(v.z - __half2float(hz));
                __half lw = __float2half_rn(v.w - __half2float(hw));
                *reinterpret_cast<__half2*>(&Bl[lrow][kk])     = __halves2half2(lx, ly);
                *reinterpret_cast<__half2*>(&Bl[lrow][kk + 2]) = __halves2half2(lz, lw);
            }
        }
    };

    do_loads(0);
    do_store();
    __syncthreads();

    for (int itr = 0; itr < 16; itr++) {
        if (itr < 15) do_loads((itr + 1) * 32);  // staged; latency overlaps mma below

        // ---- compute on current smem tile: 2 x k16 steps ----
#pragma unroll
        for (int s = 0; s < 2; s++) {
            const int kb = s * 16;
            uint32_t bhf[4][2], blf[4][2];
#pragma unroll
            for (int j = 0; j < 4; j++) {
                int n0 = wn + j * 8 + g;
                bhf[j][0] = *reinterpret_cast<const uint32_t*>(&Bh[n0][kb + tg * 2]);
                bhf[j][1] = *reinterpret_cast<const uint32_t*>(&Bh[n0][kb + 8 + tg * 2]);
                blf[j][0] = *reinterpret_cast<const uint32_t*>(&Bl[n0][kb + tg * 2]);
                blf[j][1] = *reinterpret_cast<const uint32_t*>(&Bl[n0][kb + 8 + tg * 2]);
            }
#pragma unroll
            for (int i = 0; i < 4; i++) {
                int r0 = wm + i * 16 + g;
                uint32_t ahf[4] = {
                    *reinterpret_cast<const uint32_t*>(&Ah[r0][kb + tg * 2]),
                    *reinterpret_cast<const uint32_t*>(&Ah[r0 + 8][kb + tg * 2]),
                    *reinterpret_cast<const uint32_t*>(&Ah[r0][kb + 8 + tg * 2]),
                    *reinterpret_cast<const uint32_t*>(&Ah[r0 + 8][kb + 8 + tg * 2])};
                uint32_t alf[4] = {
                    *reinterpret_cast<const uint32_t*>(&Al[r0][kb + tg * 2]),
                    *reinterpret_cast<const uint32_t*>(&Al[r0 + 8][kb + tg * 2]),
                    *reinterpret_cast<const uint32_t*>(&Al[r0][kb + 8 + tg * 2]),
                    *reinterpret_cast<const uint32_t*>(&Al[r0 + 8][kb + 8 + tg * 2])};
#pragma unroll
                for (int j = 0; j < 4; j++) {
                    mma_f16(acc[i][j], ahf, bhf[j]);  // hi*hi
                    mma_f16(acc[i][j], ahf, blf[j]);  // hi*lo
                    mma_f16(acc[i][j], alf, bhf[j]);  // lo*hi
                }
            }
        }
        __syncthreads();           // everyone done reading this tile
        if (itr < 15) {
            do_store();            // overwrite with staged next tile
            __syncthreads();
        }
    }

    // ---- epilogue (same fragment layout as before) ----
#pragma unroll
    for (int i = 0; i < 4; i++) {
        int r0 = wm + i * 16 + g;
#pragma unroll
        for (int j = 0; j < 4; j++) {
            int n0 = wn + j * 8 + (tg << 1);
            *reinterpret_cast<float2*>(Cp + (size_t)r0 * 512 + n0) =
                make_float2(acc[i][j][0], acc[i][j][1]);
            *reinterpret_cast<float2*>(Cp + (size_t)(r0 + 8) * 512 + n0) =
                make_float2(acc[i][j][2], acc[i][j][3]);
        }
    }
}

// Q[b] = dec[b] @ W^T  — fp16x3 split
__global__ __launch_bounds__(256, 2) void k_query(const float* __restrict__ dec,
                                                  const float* __restrict__ W) {
    size_t b = blockIdx.z;
    split_gemm_nt(dec + b * NPRED * NDIM,
                  W + (size_t)blockIdx.x * 128 * 512,
                  g_Q + b * NPRED * NDIM + blockIdx.x * 128);
}

// S[b] = Q[b] @ enc[b]^T  — fp16x3 split
__global__ __launch_bounds__(256, 2) void k_scores(const float* __restrict__ enc) {
    size_t b = blockIdx.z;
    split_gemm_nt(g_Q + b * NPRED * NDIM,
                  enc + b * NSRC * NDIM + (size_t)blockIdx.x * 128 * 512,
                  g_S + b * NPRED * NSRC + blockIdx.x * 128);
}

// ============================================================================
// Context: C[b] = P[b] @ enc[b], single-pass TF32 (unchanged, known-good).
// ============================================================================
__device__ __forceinline__ void gemm_nn_tf32(const float* __restrict__ Ab,
                                             const float* __restrict__ Bb,
                                             float* __restrict__ Cb) {
    constexpr int ASTR = 20;
    constexpr int BSTR = 136;

    __shared__ uint32_t As_h[128][ASTR];
    __shared__ uint32_t Bs_h[16][BSTR];

    const int tid  = threadIdx.x;
    const int lane = tid & 31;
    const int warp = tid >> 5;
    const int wm = (warp >> 2) << 6;
    const int wn = (warp & 3) << 5;

    const float* Bp = Bb + blockIdx.x * 128;
    float* Cp = Cb + blockIdx.x * 128;

    float acc[4][4][4];
#pragma unroll
    for (int i = 0; i < 4; i++)
#pragma unroll
        for (int j = 0; j < 4; j++)
#pragma unroll
            for (int r = 0; r < 4; r++) acc[i][j][r] = 0.0f;

    const int alr = tid >> 2;
    const int alc = (tid & 3) << 2;
    const int blr = tid >> 5;
    const int blc = lane << 2;

    for (int k0 = 0; k0 < 512; k0 += 16) {
#pragma unroll
        for (int it = 0; it < 2; it++) {
            int row = alr + it * 64;
            float4 v = *reinterpret_cast<const float4*>(Ab + (size_t)row * 512 + k0 + alc);
            *reinterpret_cast<uint4*>(&As_h[row][alc]) =
                make_uint4(f2tf(v.x), f2tf(v.y), f2tf(v.z), f2tf(v.w));
        }
#pragma unroll
        for (int it = 0; it < 2; it++) {
            int row = blr + it * 8;
            float4 v = *reinterpret_cast<const float4*>(Bp + (size_t)(k0 + row) * 512 + blc);
            *reinterpret_cast<uint4*>(&Bs_h[row][blc]) =
                make_uint4(f2tf(v.x), f2tf(v.y), f2tf(v.z), f2tf(v.w));
        }
        __syncthreads();

#pragma unroll
        for (int kk = 0; kk < 2; kk++) {
            const int c0 = kk * 8 + (lane & 3);
            const int g4 = lane >> 2;
            uint32_t bh[4][2];
#pragma unroll
            for (int j = 0; j < 4; j++) {
                int n0 = wn + j * 8 + g4;
                bh[j][0] = Bs_h[c0][n0];
                bh[j][1] = Bs_h[c0 + 4][n0];
            }
#pragma unroll
            for (int i = 0; i < 4; i++) {
                int r0 = wm + i * 16 + g4;
                uint32_t ah[4] = {As_h[r0][c0], As_h[r0 + 8][c0],
                                  As_h[r0][c0 + 4], As_h[r0 + 8][c0 + 4]};
#pragma unroll
                for (int j = 0; j < 4; j++) mma_tf32(acc[i][j], ah, bh[j]);
            }
        }
        __syncthreads();
    }

#pragma unroll
    for (int i = 0; i < 4; i++) {
        int r0 = wm + i * 16 + (lane >> 2);
#pragma unroll
        for (int j = 0; j < 4; j++) {
            int n0 = wn + j * 8 + ((lane & 3) << 1);
            *reinterpret_cast<float2*>(Cp + (size_t)r0 * 512 + n0) =
                make_float2(acc[i][j][0], acc[i][j][1]);
            *reinterpret_cast<float2*>(Cp + (size_t)(r0 + 8) * 512 + n0) =
                make_float2(acc[i][j][2], acc[i][j][3]);
        }
    }
}

__global__ __launch_bounds__(256, 2) void k_context(const float* __restrict__ enc,
                                                    float* __restrict__ out) {
    size_t b = blockIdx.z;
    gemm_nn_tf32(g_S + b * NPRED * NSRC, enc + b * NSRC * NDIM, out + b * NPRED * NDIM);
}

// Masked softmax over SRC=512, one warp per (b, p) row, in place on g_S.
// mask is INT32 (harness converts jnp.bool_ to int32): nonzero -> masked.
__global__ __launch_bounds__(256) void k_softmax(const int* __restrict__ mask) {
    int gw = (blockIdx.x * 256 + threadIdx.x) >> 5;
    int lane = threadIdx.x & 31;
    float* row = g_S + (size_t)gw * NSRC;
    const int* mrow = mask + (size_t)(gw >> 7) * NSRC;

    float v[16];
    float m = -1e30f;
#pragma unroll
    for (int i = 0; i < 4; i++) {
        int s = i * 128 + lane * 4;
        float4 x = *reinterpret_cast<const float4*>(row + s);
        int4 mk = *reinterpret_cast<const int4*>(mrow + s);
        v[i * 4 + 0] = mk.x ? -1e30f : x.x;
        v[i * 4 + 1] = mk.y ? -1e30f : x.y;
        v[i * 4 + 2] = mk.z ? -1e30f : x.z;
        v[i * 4 + 3] = mk.w ? -1e30f : x.w;
        m = fmaxf(m, fmaxf(fmaxf(v[i * 4 + 0], v[i * 4 + 1]),
                           fmaxf(v[i * 4 + 2], v[i * 4 + 3])));
    }
#pragma unroll
    for (int o = 16; o; o >>= 1) m = fmaxf(m, __shfl_xor_sync(0xffffffffu, m, o));

    float sum = 0.0f;
#pragma unroll
    for (int i = 0; i < 16; i++) {
        v[i] = __expf(v[i] - m);
        sum += v[i];
    }
#pragma unroll
    for (int o = 16; o; o >>= 1) sum += __shfl_xor_sync(0xffffffffu, sum, o);
    float inv = 1.0f / sum;

#pragma unroll
    for (int i = 0; i < 4; i++) {
        int s = i * 128 + lane * 4;
        *reinterpret_cast<float4*>(row + s) =
            make_float4(v[i * 4 + 0] * inv, v[i * 4 + 1] * inv,
                        v[i * 4 + 2] * inv, v[i * 4 + 3] * inv);
    }
}

extern "C" void kernel_launch(void* const* d_in, const int* in_sizes, int n_in,
                              void* d_out, int out_size) {
    const float* enc = nullptr;
    const float* dec = nullptr;
    const float* W = nullptr;
    const int* mask = nullptr;
    for (int i = 0; i < n_in; i++) {
        int n = in_sizes[i];
        if (n == NBATCH * NSRC * NDIM)        enc  = (const float*)d_in[i];
        else if (n == NBATCH * NPRED * NDIM)  dec  = (const float*)d_in[i];
        else if (n == NDIM * NDIM)            W    = (const float*)d_in[i];
        else if (n == NBATCH * NSRC)          mask = (const int*)d_in[i];
    }
    float* out = (float*)d_out;

    dim3 g(4, 1, NBATCH);
    k_query<<<g, 256>>>(dec, W);
    k_scores<<<g, 256>>>(enc);
    k_softmax<<<(NBATCH * NPRED) / 8, 256>>>(mask);
    k_context<<<g, 256>>>(enc, out);
}

// round 9
// speedup vs baseline: 1.3828x; 1.0485x over previous
#include <cuda_runtime.h>
#include <cuda_fp16.h>
#include <cstdint>

#define NBATCH 256
#define NSRC   512
#define NPRED  128
#define NDIM   512

static __device__ __align__(128) float g_Q[(size_t)NBATCH * NPRED * NDIM];  // 67 MB
static __device__ __align__(128) float g_S[(size_t)NBATCH * NPRED * NSRC];  // 67 MB

__device__ __forceinline__ void mma_f16(float (&d)[4], const uint32_t* a, const uint32_t* b) {
    asm volatile(
        "mma.sync.aligned.m16n8k16.row.col.f32.f16.f16.f32 "
        "{%0,%1,%2,%3}, {%4,%5,%6,%7}, {%8,%9}, {%0,%1,%2,%3};\n"
        : "+f"(d[0]), "+f"(d[1]), "+f"(d[2]), "+f"(d[3])
        : "r"(a[0]), "r"(a[1]), "r"(a[2]), "r"(a[3]), "r"(b[0]), "r"(b[1]));
}

__device__ __forceinline__ uint32_t saddr(const void* p) {
    return (uint32_t)__cvta_generic_to_shared(p);
}

__device__ __forceinline__ void ldsm4(uint32_t& r0, uint32_t& r1, uint32_t& r2, uint32_t& r3,
                                      uint32_t a) {
    asm volatile("ldmatrix.sync.aligned.m8n8.x4.shared.b16 {%0,%1,%2,%3}, [%4];"
                 : "=r"(r0), "=r"(r1), "=r"(r2), "=r"(r3) : "r"(a));
}

__device__ __forceinline__ void ldsm4t(uint32_t& r0, uint32_t& r1, uint32_t& r2, uint32_t& r3,
                                       uint32_t a) {
    asm volatile("ldmatrix.sync.aligned.m8n8.x4.trans.shared.b16 {%0,%1,%2,%3}, [%4];"
                 : "=r"(r0), "=r"(r1), "=r"(r2), "=r"(r3) : "r"(a));
}

__device__ __forceinline__ __half2 hi2(float a, float b) {
    return __halves2half2(__float2half_rn(a), __float2half_rn(b));
}
__device__ __forceinline__ __half2 lo2(float a, float b, __half2 h) {
    return __halves2half2(__float2half_rn(a - __half2float(__low2half(h))),
                          __float2half_rn(b - __half2float(__high2half(h))));
}

// ============================================================================
// fp16 hi/lo split GEMM-NT (score path): C(128x512 slice) = A(128x512) * B^T.
// Fragments via ldmatrix; BK=32; register-staged global loads.
// ============================================================================
#define HPAD 40  // fp16 row stride: 8-row LDSM groups hit disjoint bank spans

__device__ __forceinline__ void split_gemm_nt(const float* __restrict__ Ab,
                                              const float* __restrict__ Bp,
                                              float* __restrict__ Cp) {
    __shared__ __half Ah[128][HPAD], Al[128][HPAD];
    __shared__ __half Bh[128][HPAD], Bl[128][HPAD];

    const int tid  = threadIdx.x;
    const int lane = tid & 31;
    const int warp = tid >> 5;
    const int wm = (warp >> 2) << 6;   // 0 or 64
    const int wn = (warp & 3) << 5;    // 0,32,64,96
    const int g  = lane >> 2;
    const int tg = lane & 3;

    // ldmatrix per-lane address components
    const int a_r = lane & 15;                      // row within 16-row frag
    const int a_c = (lane >> 4) << 3;               // 0 or 8 (k halves)
    const int b_r = (lane & 7) + ((lane & 16) >> 1);// row within 16-n pair
    const int b_c = lane & 8;                       // 0 or 8 (k halves)

    const uint32_t ah_b = saddr(&Ah[0][0]);
    const uint32_t al_b = saddr(&Al[0][0]);
    const uint32_t bh_b = saddr(&Bh[0][0]);
    const uint32_t bl_b = saddr(&Bl[0][0]);

    const int lrow = tid >> 1;
    const int lk0  = (tid & 1) << 4;

    float acc[4][4][4];
#pragma unroll
    for (int i = 0; i < 4; i++)
#pragma unroll
        for (int j = 0; j < 4; j++)
#pragma unroll
            for (int r = 0; r < 4; r++) acc[i][j][r] = 0.0f;

    float4 sa[4], sb[4];

    auto do_loads = [&](int k0) {
#pragma unroll
        for (int it = 0; it < 4; it++) {
            sa[it] = *reinterpret_cast<const float4*>(Ab + (size_t)lrow * 512 + k0 + lk0 + it * 4);
            sb[it] = *reinterpret_cast<const float4*>(Bp + (size_t)lrow * 512 + k0 + lk0 + it * 4);
        }
    };

    auto do_store = [&]() {
#pragma unroll
        for (int it = 0; it < 4; it++) {
            int kk = lk0 + it * 4;
            {
                float4 v = sa[it];
                __half2 h0 = hi2(v.x, v.y), h1 = hi2(v.z, v.w);
                *reinterpret_cast<__half2*>(&Ah[lrow][kk])     = h0;
                *reinterpret_cast<__half2*>(&Ah[lrow][kk + 2]) = h1;
                *reinterpret_cast<__half2*>(&Al[lrow][kk])     = lo2(v.x, v.y, h0);
                *reinterpret_cast<__half2*>(&Al[lrow][kk + 2]) = lo2(v.z, v.w, h1);
            }
            {
                float4 v = sb[it];
                __half2 h0 = hi2(v.x, v.y), h1 = hi2(v.z, v.w);
                *reinterpret_cast<__half2*>(&Bh[lrow][kk])     = h0;
                *reinterpret_cast<__half2*>(&Bh[lrow][kk + 2]) = h1;
                *reinterpret_cast<__half2*>(&Bl[lrow][kk])     = lo2(v.x, v.y, h0);
                *reinterpret_cast<__half2*>(&Bl[lrow][kk + 2]) = lo2(v.z, v.w, h1);
            }
        }
    };

    do_loads(0);
    do_store();
    __syncthreads();

    for (int itr = 0; itr < 16; itr++) {
        if (itr < 15) do_loads((itr + 1) * 32);

#pragma unroll
        for (int s = 0; s < 2; s++) {
            const int kb = s * 16;
            uint32_t bh[2][4], bl[2][4];
#pragma unroll
            for (int jp = 0; jp < 2; jp++) {
                uint32_t off = (uint32_t)(((wn + jp * 16 + b_r) * HPAD + kb + b_c) << 1);
                ldsm4(bh[jp][0], bh[jp][1], bh[jp][2], bh[jp][3], bh_b + off);
                ldsm4(bl[jp][0], bl[jp][1], bl[jp][2], bl[jp][3], bl_b + off);
            }
#pragma unroll
            for (int i = 0; i < 4; i++) {
                uint32_t off = (uint32_t)(((wm + i * 16 + a_r) * HPAD + kb + a_c) << 1);
                uint32_t ah[4], al[4];
                ldsm4(ah[0], ah[1], ah[2], ah[3], ah_b + off);
                ldsm4(al[0], al[1], al[2], al[3], al_b + off);
#pragma unroll
                for (int j = 0; j < 4; j++) {
                    uint32_t bhf[2] = {bh[j >> 1][(j & 1) << 1], bh[j >> 1][((j & 1) << 1) + 1]};
                    uint32_t blf[2] = {bl[j >> 1][(j & 1) << 1], bl[j >> 1][((j & 1) << 1) + 1]};
                    mma_f16(acc[i][j], ah, bhf);
                    mma_f16(acc[i][j], ah, blf);
                    mma_f16(acc[i][j], al, bhf);
                }
            }
        }
        __syncthreads();
        if (itr < 15) {
            do_store();
            __syncthreads();
        }
    }

#pragma unroll
    for (int i = 0; i < 4; i++) {
        int r0 = wm + i * 16 + g;
#pragma unroll
        for (int j = 0; j < 4; j++) {
            int n0 = wn + j * 8 + (tg << 1);
            *reinterpret_cast<float2*>(Cp + (size_t)r0 * 512 + n0) =
                make_float2(acc[i][j][0], acc[i][j][1]);
            *reinterpret_cast<float2*>(Cp + (size_t)(r0 + 8) * 512 + n0) =
                make_float2(acc[i][j][2], acc[i][j][3]);
        }
    }
}

__global__ __launch_bounds__(256, 2) void k_query(const float* __restrict__ dec,
                                                  const float* __restrict__ W) {
    size_t b = blockIdx.z;
    split_gemm_nt(dec + b * NPRED * NDIM,
                  W + (size_t)blockIdx.x * 128 * 512,
                  g_Q + b * NPRED * NDIM + blockIdx.x * 128);
}

__global__ __launch_bounds__(256, 2) void k_scores(const float* __restrict__ enc) {
    size_t b = blockIdx.z;
    split_gemm_nt(g_Q + b * NPRED * NDIM,
                  enc + b * NSRC * NDIM + (size_t)blockIdx.x * 128 * 512,
                  g_S + b * NPRED * NSRC + blockIdx.x * 128);
}

// ============================================================================
// Context NN: C(128 x 128-slice) = P(128x512) * enc(512 x 512), fp16 2-term:
// C = Ph*Eh + Ph*El  (P quantization dominates; same 11-bit budget as tf32).
// A frags via ldmatrix, B (k-major) frags via ldmatrix.trans.
// ============================================================================
#define ESTR 136  // enc tile fp16 row stride (k-major): 68-word stride, conflict-free

__global__ __launch_bounds__(256, 2) void k_context(const float* __restrict__ enc,
                                                    float* __restrict__ out) {
    __shared__ __half Ph[128][HPAD];
    __shared__ __half Eh[32][ESTR], El[32][ESTR];

    const size_t b = blockIdx.z;
    const float* Ab = g_S + b * NPRED * NSRC;
    const float* Bb = enc + b * NSRC * NDIM + blockIdx.x * 128;
    float* Cp = out + b * NPRED * NDIM + blockIdx.x * 128;

    const int tid  = threadIdx.x;
    const int lane = tid & 31;
    const int warp = tid >> 5;
    const int wm = (warp >> 2) << 6;
    const int wn = (warp & 3) << 5;
    const int g  = lane >> 2;
    const int tg = lane & 3;

    const int a_r = lane & 15;
    const int a_c = (lane >> 4) << 3;
    const int bt_r = (lane & 7) + (lane & 8);   // k-row within 16
    const int bt_c = (lane >> 4) << 3;          // n offset 0/8

    const uint32_t ph_b = saddr(&Ph[0][0]);
    const uint32_t eh_b = saddr(&Eh[0][0]);
    const uint32_t el_b = saddr(&El[0][0]);

    const int arow = tid >> 1;            // 0..127
    const int ak0  = (tid & 1) << 4;
    const int brow = tid >> 3;            // 0..31
    const int bn0  = (tid & 7) << 4;

    float acc[4][4][4];
#pragma unroll
    for (int i = 0; i < 4; i++)
#pragma unroll
        for (int j = 0; j < 4; j++)
#pragma unroll
            for (int r = 0; r < 4; r++) acc[i][j][r] = 0.0f;

    float4 sa[4], sb[4];

    auto do_loads = [&](int k0) {
#pragma unroll
        for (int it = 0; it < 4; it++) {
            sa[it] = *reinterpret_cast<const float4*>(Ab + (size_t)arow * 512 + k0 + ak0 + it * 4);
            sb[it] = *reinterpret_cast<const float4*>(Bb + (size_t)(k0 + brow) * 512 + bn0 + it * 4);
        }
    };

    auto do_store = [&]() {
#pragma unroll
        for (int it = 0; it < 4; it++) {
            {
                int kk = ak0 + it * 4;
                float4 v = sa[it];
                *reinterpret_cast<__half2*>(&Ph[arow][kk])     = hi2(v.x, v.y);
                *reinterpret_cast<__half2*>(&Ph[arow][kk + 2]) = hi2(v.z, v.w);
            }
            {
                int nn = bn0 + it * 4;
                float4 v = sb[it];
                __half2 h0 = hi2(v.x, v.y), h1 = hi2(v.z, v.w);
                *reinterpret_cast<__half2*>(&Eh[brow][nn])     = h0;
                *reinterpret_cast<__half2*>(&Eh[brow][nn + 2]) = h1;
                *reinterpret_cast<__half2*>(&El[brow][nn])     = lo2(v.x, v.y, h0);
                *reinterpret_cast<__half2*>(&El[brow][nn + 2]) = lo2(v.z, v.w, h1);
            }
        }
    };

    do_loads(0);
    do_store();
    __syncthreads();

    for (int itr = 0; itr < 16; itr++) {
        if (itr < 15) do_loads((itr + 1) * 32);

#pragma unroll
        for (int s = 0; s < 2; s++) {
            const int kb = s * 16;
            uint32_t bh[2][4], bl[2][4];
#pragma unroll
            for (int jp = 0; jp < 2; jp++) {
                uint32_t off = (uint32_t)(((kb + bt_r) * ESTR + wn + jp * 16 + bt_c) << 1);
                ldsm4t(bh[jp][0], bh[jp][1], bh[jp][2], bh[jp][3], eh_b + off);
                ldsm4t(bl[jp][0], bl[jp][1], bl[jp][2], bl[jp][3], el_b + off);
            }
#pragma unroll
            for (int i = 0; i < 4; i++) {
                uint32_t off = (uint32_t)(((wm + i * 16 + a_r) * HPAD + kb + a_c) << 1);
                uint32_t ap[4];
                ldsm4(ap[0], ap[1], ap[2], ap[3], ph_b + off);
#pragma unroll
                for (int j = 0; j < 4; j++) {
                    uint32_t bhf[2] = {bh[j >> 1][(j & 1) << 1], bh[j >> 1][((j & 1) << 1) + 1]};
                    uint32_t blf[2] = {bl[j >> 1][(j & 1) << 1], bl[j >> 1][((j & 1) << 1) + 1]};
                    mma_f16(acc[i][j], ap, bhf);
                    mma_f16(acc[i][j], ap, blf);
                }
            }
        }
        __syncthreads();
        if (itr < 15) {
            do_store();
            __syncthreads();
        }
    }

#pragma unroll
    for (int i = 0; i < 4; i++) {
        int r0 = wm + i * 16 + g;
#pragma unroll
        for (int j = 0; j < 4; j++) {
            int n0 = wn + j * 8 + (tg << 1);
            *reinterpret_cast<float2*>(Cp + (size_t)r0 * 512 + n0) =
                make_float2(acc[i][j][0], acc[i][j][1]);
            *reinterpret_cast<float2*>(Cp + (size_t)(r0 + 8) * 512 + n0) =
                make_float2(acc[i][j][2], acc[i][j][3]);
        }
    }
}

// Masked softmax over SRC=512, one warp per (b, p) row, in place on g_S.
__global__ __launch_bounds__(256) void k_softmax(const int* __restrict__ mask) {
    int gw = (blockIdx.x * 256 + threadIdx.x) >> 5;
    int lane = threadIdx.x & 31;
    float* row = g_S + (size_t)gw * NSRC;
    const int* mrow = mask + (size_t)(gw >> 7) * NSRC;

    float v[16];
    float m = -1e30f;
#pragma unroll
    for (int i = 0; i < 4; i++) {
        int s = i * 128 + lane * 4;
        float4 x = *reinterpret_cast<const float4*>(row + s);
        int4 mk = *reinterpret_cast<const int4*>(mrow + s);
        v[i * 4 + 0] = mk.x ? -1e30f : x.x;
        v[i * 4 + 1] = mk.y ? -1e30f : x.y;
        v[i * 4 + 2] = mk.z ? -1e30f : x.z;
        v[i * 4 + 3] = mk.w ? -1e30f : x.w;
        m = fmaxf(m, fmaxf(fmaxf(v[i * 4 + 0], v[i * 4 + 1]),
                           fmaxf(v[i * 4 + 2], v[i * 4 + 3])));
    }
#pragma unroll
    for (int o = 16; o; o >>= 1) m = fmaxf(m, __shfl_xor_sync(0xffffffffu, m, o));

    float sum = 0.0f;
#pragma unroll
    for (int i = 0; i < 16; i++) {
        v[i] = __expf(v[i] - m);
        sum += v[i];
    }
#pragma unroll
    for (int o = 16; o; o >>= 1) sum += __shfl_xor_sync(0xffffffffu, sum, o);
    float inv = 1.0f / sum;

#pragma unroll
    for (int i = 0; i < 4; i++) {
        int s = i * 128 + lane * 4;
        *reinterpret_cast<float4*>(row + s) =
            make_float4(v[i * 4 + 0] * inv, v[i * 4 + 1] * inv,
                        v[i * 4 + 2] * inv, v[i * 4 + 3] * inv);
    }
}

extern "C" void kernel_launch(void* const* d_in, const int* in_sizes, int n_in,
                              void* d_out, int out_size) {
    const float* enc = nullptr;
    const float* dec = nullptr;
    const float* W = nullptr;
    const int* mask = nullptr;
    for (int i = 0; i < n_in; i++) {
        int n = in_sizes[i];
        if (n == NBATCH * NSRC * NDIM)        enc  = (const float*)d_in[i];
        else if (n == NBATCH * NPRED * NDIM)  dec  = (const float*)d_in[i];
        else if (n == NDIM * NDIM)            W    = (const float*)d_in[i];
        else if (n == NBATCH * NSRC)          mask = (const int*)d_in[i];
    }
    float* out = (float*)d_out;

    dim3 g(4, 1, NBATCH);
    k_query<<<g, 256>>>(dec, W);
    k_scores<<<g, 256>>>(enc);
    k_softmax<<<(NBATCH * NPRED) / 8, 256>>>(mask);
    k_context<<<g, 256>>>(enc, out);
}